// round 4
// baseline (speedup 1.0000x reference)
#include <cuda_runtime.h>
#include <math.h>

#define NB 4
#define CH 128
#define HH 96
#define WW 96
#define S  48
#define L  2304
#define LLn 5308416   // L*L
#define CHK 36
#define CR  64

// ---- scratch (static device globals; no allocation) ----
__device__ float g_A [(size_t)NB * LLn];
__device__ float g_B2[(size_t)NB * LLn];
__device__ float g_Bs[NB * CH * L];
__device__ float g_Fs[NB * CH * L];
__device__ float g_bcl[NB * HH * WW * CH];
__device__ float g_sq [NB * L];
__device__ float g_invn[NB * L];
__device__ float g_mmv[NB * L];
__device__ float g_pmax[NB * CHK * L];
__device__ float g_psum[NB * CHK * L];
__device__ float g_cmax[NB * L];
__device__ float g_sinv[NB * L];
__device__ int   g_ccnt[NB * L * CHK];
__device__ int   g_lidx[(size_t)NB * L * CHK * CR];
__device__ float g_lw  [(size_t)NB * L * CHK * CR];

// ---- subsample b,f at stride 2 -> [i][c][l] ----
__global__ void k_sub(const float* __restrict__ b, const float* __restrict__ f) {
    int idx = blockIdx.x * blockDim.x + threadIdx.x;   // NB*CH*L
    int l = idx % L;
    int t = idx / L;
    int c = t % CH;
    int i = t / CH;
    int r = l / S, cc = l % S;
    int src = ((i * CH + c) * HH + 2 * r) * WW + 2 * cc;
    g_Bs[idx] = b[src];
    g_Fs[idx] = f[src];
}

// ---- channel-last copy of b: bcl[i][y][x][c] ----
__global__ void k_bcl(const float* __restrict__ b) {
    int idx = blockIdx.x * blockDim.x + threadIdx.x;   // NB*CH*HH*WW
    int x = idx % WW;
    int t = idx / WW;
    int y = t % HH;
    int u = t / HH;
    int c = u % CH;
    int i = u / CH;
    g_bcl[((i * HH + y) * WW + x) * CH + c] = b[idx];
}

// ---- per-pixel channel sum of Bs^2 ----
__global__ void k_sq(void) {
    int idx = blockIdx.x * blockDim.x + threadIdx.x;   // NB*L
    int i = idx / L, l = idx % L;
    const float* p = g_Bs + (size_t)i * CH * L + l;
    float s = 0.f;
#pragma unroll 8
    for (int c = 0; c < CH; ++c) { float v = p[(size_t)c * L]; s += v * v; }
    g_sq[idx] = s;
}

// ---- inv patch norm: 1/sqrt(valid-3x3-boxsum(sq) + 1152*1e-4) ----
__global__ void k_norm(void) {
    int idx = blockIdx.x * blockDim.x + threadIdx.x;
    int i = idx / L, l = idx % L;
    int r = l / S, c = l % S;
    float s = 0.f;
    for (int dr = -1; dr <= 1; ++dr)
        for (int dc = -1; dc <= 1; ++dc) {
            int rr = r + dr, cc = c + dc;
            if ((unsigned)rr < S && (unsigned)cc < S) s += g_sq[i * L + rr * S + cc];
        }
    g_invn[idx] = rsqrtf(s + 0.1152f);
}

// ---- mask validity mm[l] ----
__global__ void k_mm(const float* __restrict__ mask) {
    int idx = blockIdx.x * blockDim.x + threadIdx.x;
    int i = idx / L, l = idx % L;
    int r = l / S, c = l % S;
    float s = 0.f;
    for (int dr = -1; dr <= 1; ++dr)
        for (int dc = -1; dc <= 1; ++dc) {
            int rr = r + dr, cc = c + dc;
            if ((unsigned)rr < S && (unsigned)cc < S)
                s += mask[i * HH * WW + (2 * rr) * WW + (2 * cc)];
        }
    g_mmv[idx] = (s * (1.0f / 9.0f) == 1.0f) ? 1.f : 0.f;
}

// ---- G = Bs^T * Fs : [L x L] per sample, f32, 128x128 tiles ----
__global__ __launch_bounds__(256) void k_gemm(void) {
    int i = blockIdx.z;
    const float* A  = g_Bs + (size_t)i * CH * L;
    const float* Bm = g_Fs + (size_t)i * CH * L;
    float* Cc = g_A + (size_t)i * LLn;
    int m0 = blockIdx.y * 128, n0 = blockIdx.x * 128;
    __shared__ float sA[16][128], sB[16][128];
    int tid = threadIdx.x;
    int tx = tid & 15, ty = tid >> 4;
    int lr = tid >> 5, lc = (tid & 31) << 2;
    float acc[8][8] = {};
    for (int k0 = 0; k0 < CH; k0 += 16) {
#pragma unroll
        for (int sdx = 0; sdx < 2; ++sdx) {
            int kk = lr + sdx * 8;
            *(float4*)&sA[kk][lc] = *(const float4*)&A [(size_t)(k0 + kk) * L + m0 + lc];
            *(float4*)&sB[kk][lc] = *(const float4*)&Bm[(size_t)(k0 + kk) * L + n0 + lc];
        }
        __syncthreads();
#pragma unroll
        for (int kk = 0; kk < 16; ++kk) {
            float av[8], bv[8];
            *(float4*)&av[0] = *(float4*)&sA[kk][ty * 8];
            *(float4*)&av[4] = *(float4*)&sA[kk][ty * 8 + 4];
            *(float4*)&bv[0] = *(float4*)&sB[kk][tx * 8];
            *(float4*)&bv[4] = *(float4*)&sB[kk][tx * 8 + 4];
#pragma unroll
            for (int mi = 0; mi < 8; ++mi)
#pragma unroll
                for (int ni = 0; ni < 8; ++ni)
                    acc[mi][ni] = fmaf(av[mi], bv[ni], acc[mi][ni]);
        }
        __syncthreads();
    }
#pragma unroll
    for (int mi = 0; mi < 8; ++mi) {
        float* cp = &Cc[(size_t)(m0 + ty * 8 + mi) * L + n0 + tx * 8];
        float4 v0 = {acc[mi][0], acc[mi][1], acc[mi][2], acc[mi][3]};
        float4 v1 = {acc[mi][4], acc[mi][5], acc[mi][6], acc[mi][7]};
        *(float4*)cp = v0; *(float4*)(cp + 4) = v1;
    }
}

// ---- patch correlation: 9-tap masked diagonal band of G, * invn[a] : g_A -> g_B2 ----
__global__ void k_corr(void) {
    int b = blockIdx.x * 256 + threadIdx.x;
    int a = blockIdx.y, i = blockIdx.z;
    const float* src = g_A + (size_t)i * LLn;
    int r1 = a / S, c1 = a % S, r2 = b / S, c2 = b % S;
    float s = 0.f;
#pragma unroll
    for (int dr = -1; dr <= 1; ++dr) {
        if ((unsigned)(r1 + dr) >= S || (unsigned)(r2 + dr) >= S) continue;
#pragma unroll
        for (int dc = -1; dc <= 1; ++dc) {
            if ((unsigned)(c1 + dc) >= S || (unsigned)(c2 + dc) >= S) continue;
            int off = dr * S + dc;
            s += src[(size_t)(a + off) * L + (b + off)];
        }
    }
    g_B2[(size_t)i * LLn + (size_t)a * L + b] = s * g_invn[i * L + a];
}

// ---- fused fuse_diag x2 (flat then transposed-flat) + logit scale : g_B2 -> g_A ----
__global__ void k_fuse(void) {
    int b = blockIdx.x * 256 + threadIdx.x;
    int a = blockIdx.y, i = blockIdx.z;
    const float* src = g_B2 + (size_t)i * LLn;
    int aT = (a % S) * S + a / S;
    int bT = (b % S) * S + b / S;
    float s = 0.f;
#pragma unroll
    for (int d2 = -1; d2 <= 1; ++d2) {
        int ta = aT + d2, tb = bT + d2;
        if ((unsigned)ta >= L || (unsigned)tb >= L) continue;
        int A2 = (ta % S) * S + ta / S;
        int B2 = (tb % S) * S + tb / S;
#pragma unroll
        for (int d1 = -1; d1 <= 1; ++d1) {
            int x = A2 + d1, y = B2 + d1;
            if ((unsigned)x >= L || (unsigned)y >= L) continue;
            s += src[(size_t)x * L + y];
        }
    }
    g_A[(size_t)i * LLn + (size_t)a * L + b] = s * 10.0f * g_mmv[i * L + a];
}

// ---- softmax stage 1: chunked column max ----
__global__ void k_max1(void) {
    int b = blockIdx.x * 256 + threadIdx.x;
    int ch = blockIdx.y, i = blockIdx.z;
    const float* src = g_A + (size_t)i * LLn;
    float m = -1e30f;
#pragma unroll 8
    for (int r = 0; r < CR; ++r)
        m = fmaxf(m, src[(size_t)(ch * CR + r) * L + b]);
    g_pmax[(i * CHK + ch) * L + b] = m;
}
__global__ void k_max2(void) {
    int b = blockIdx.x * 256 + threadIdx.x;
    int i = blockIdx.y;
    float m = -1e30f;
#pragma unroll
    for (int ch = 0; ch < CHK; ++ch)
        m = fmaxf(m, g_pmax[(i * CHK + ch) * L + b]);
    g_cmax[i * L + b] = m;
}

// ---- softmax stage 2: partial sums + deterministic candidate extraction ----
__global__ void k_ext(void) {
    int b = blockIdx.x * 256 + threadIdx.x;
    int ch = blockIdx.y, i = blockIdx.z;
    const float* src = g_A + (size_t)i * LLn;
    float m = g_cmax[i * L + b];
    float s = 0.f;
    int n = 0;
    size_t base = ((size_t)(i * L + b) * CHK + ch) * CR;
    for (int r = 0; r < CR; ++r) {
        int a = ch * CR + r;
        float d = src[(size_t)a * L + b] - m;
        if (d > -25.0f) {
            float e = __expf(d);
            s += e;
            if (g_mmv[i * L + a] > 0.5f) {
                g_lidx[base + n] = a;
                g_lw [base + n] = e;
                n++;
            }
        }
    }
    g_psum[(i * CHK + ch) * L + b] = s;
    g_ccnt[(i * L + b) * CHK + ch] = n;
}
__global__ void k_sum2(void) {
    int b = blockIdx.x * 256 + threadIdx.x;
    int i = blockIdx.y;
    float s = 0.f;
#pragma unroll
    for (int ch = 0; ch < CHK; ++ch)
        s += g_psum[(i * CHK + ch) * L + b];
    g_sinv[i * L + b] = 1.0f / s;
}

// ---- sparse transposed-conv gather ----
__global__ __launch_bounds__(128) void k_out(float* __restrict__ out) {
    int p = blockIdx.x;            // 0..HH*WW-1
    int i = blockIdx.y;
    int c = threadIdx.x;
    int oy = p / WW, ox = p % WW;
    int ua = oy / 2 - 1 + (oy & 1);
    int va = ox / 2 - 1 + (ox & 1);
    float acc = 0.f;
    const float* bcl = g_bcl + (size_t)i * HH * WW * CH;
#pragma unroll
    for (int du = 0; du < 2; ++du) {
        int uu = ua + du;
        if ((unsigned)uu >= S) continue;
#pragma unroll
        for (int dv = 0; dv < 2; ++dv) {
            int vv = va + dv;
            if ((unsigned)vv >= S) continue;
            int bcol = uu * S + vv;
            float inv = g_sinv[i * L + bcol];
            const int* cnt = &g_ccnt[(i * L + bcol) * CHK];
            size_t lb = (size_t)(i * L + bcol) * CHK * CR;
            for (int ch = 0; ch < CHK; ++ch) {
                int n = cnt[ch];
                for (int j = 0; j < n; ++j) {
                    int a   = g_lidx[lb + ch * CR + j];
                    float w = g_lw [lb + ch * CR + j] * inv;
                    int r1 = a / S, c1 = a % S;
                    int Y = oy + 2 * (r1 - uu);
                    int X = ox + 2 * (c1 - vv);
                    if ((unsigned)Y < HH && (unsigned)X < WW)
                        acc += w * bcl[((size_t)Y * WW + X) * CH + c];
                }
            }
        }
    }
    out[((size_t)(i * CH + c) * HH + oy) * WW + ox] = acc * 0.25f;
}

extern "C" void kernel_launch(void* const* d_in, const int* in_sizes, int n_in,
                              void* d_out, int out_size) {
    (void)in_sizes; (void)n_in; (void)out_size;
    const float* b    = (const float*)d_in[0];
    const float* f    = (const float*)d_in[1];
    const float* mask = (const float*)d_in[2];
    float* out = (float*)d_out;

    k_sub<<<NB * CH * L / 256, 256>>>(b, f);
    k_bcl<<<NB * CH * HH * WW / 256, 256>>>(b);
    k_sq  <<<NB * L / 256, 256>>>();
    k_norm<<<NB * L / 256, 256>>>();
    k_mm  <<<NB * L / 256, 256>>>(mask);

    dim3 gg(L / 128, L / 128, NB);
    k_gemm<<<gg, 256>>>();

    dim3 gs(L / 256, L, NB);
    k_corr<<<gs, 256>>>();
    k_fuse<<<gs, 256>>>();

    dim3 gc(L / 256, CHK, NB);
    dim3 gr(L / 256, NB);
    k_max1<<<gc, 256>>>();
    k_max2<<<gr, 256>>>();
    k_ext <<<gc, 256>>>();
    k_sum2<<<gr, 256>>>();

    dim3 go(HH * WW, NB);
    k_out<<<go, 128>>>(out);
}

// round 8
// speedup vs baseline: 1.2605x; 1.2605x over previous
#include <cuda_runtime.h>
#include <math.h>
#include <stdint.h>

#define NB 4
#define CH 128
#define HH 96
#define WW 96
#define S  48
#define L  2304
#define LLn 5308416   // L*L
#define CHK 36
#define CR  64
#define DCAP 128

// ---- scratch (static device globals; no allocation) ----
__device__ float g_A [(size_t)NB * LLn];
__device__ float g_B2[(size_t)NB * LLn];
__device__ float g_Bs[NB * CH * L];
__device__ float g_Fs[NB * CH * L];
__device__ float g_bcl[NB * HH * WW * CH];
__device__ float g_sq [NB * L];
__device__ float g_invn[NB * L];
__device__ float g_mmv[NB * L];
__device__ float g_pmax[NB * CHK * L];
__device__ float g_psum[NB * CHK * L];
__device__ int   g_ccnt[NB * CHK * L];
__device__ int   g_lidx[(size_t)NB * L * CHK * CR];
__device__ float g_lw  [(size_t)NB * L * CHK * CR];
__device__ int   g_dn  [NB * L];
__device__ int   g_didx[(size_t)NB * L * DCAP];
__device__ float g_dw  [(size_t)NB * L * DCAP];

// ================= prep kernels =================
__global__ void k_sub(const float* __restrict__ b, const float* __restrict__ f) {
    int idx = blockIdx.x * blockDim.x + threadIdx.x;   // NB*CH*L
    int l = idx % L;
    int t = idx / L;
    int c = t % CH;
    int i = t / CH;
    int r = l / S, cc = l % S;
    int src = ((i * CH + c) * HH + 2 * r) * WW + 2 * cc;
    g_Bs[idx] = b[src];
    g_Fs[idx] = f[src];
}

__global__ void k_bcl(const float* __restrict__ b) {
    int idx = blockIdx.x * blockDim.x + threadIdx.x;   // NB*CH*HH*WW
    int x = idx % WW;
    int t = idx / WW;
    int y = t % HH;
    int u = t / HH;
    int c = u % CH;
    int i = u / CH;
    g_bcl[((i * HH + y) * WW + x) * CH + c] = b[idx];
}

__global__ void k_sq(void) {
    int idx = blockIdx.x * blockDim.x + threadIdx.x;   // NB*L
    int i = idx / L, l = idx % L;
    const float* p = g_Bs + (size_t)i * CH * L + l;
    float s = 0.f;
#pragma unroll 8
    for (int c = 0; c < CH; ++c) { float v = p[(size_t)c * L]; s += v * v; }
    g_sq[idx] = s;
}

__global__ void k_norm(void) {
    int idx = blockIdx.x * blockDim.x + threadIdx.x;
    int i = idx / L, l = idx % L;
    int r = l / S, c = l % S;
    float s = 0.f;
    for (int dr = -1; dr <= 1; ++dr)
        for (int dc = -1; dc <= 1; ++dc) {
            int rr = r + dr, cc = c + dc;
            if ((unsigned)rr < S && (unsigned)cc < S) s += g_sq[i * L + rr * S + cc];
        }
    g_invn[idx] = rsqrtf(s + 0.1152f);
}

__global__ void k_mm(const float* __restrict__ mask) {
    int idx = blockIdx.x * blockDim.x + threadIdx.x;
    int i = idx / L, l = idx % L;
    int r = l / S, c = l % S;
    float s = 0.f;
    for (int dr = -1; dr <= 1; ++dr)
        for (int dc = -1; dc <= 1; ++dc) {
            int rr = r + dr, cc = c + dc;
            if ((unsigned)rr < S && (unsigned)cc < S)
                s += mask[i * HH * WW + (2 * rr) * WW + (2 * cc)];
        }
    g_mmv[idx] = (s * (1.0f / 9.0f) == 1.0f) ? 1.f : 0.f;
}

// ================= f32x2 GEMM: G = Bs^T * Fs, [L x L] per sample =================
__global__ __launch_bounds__(256) void k_gemm(void) {
    int i = blockIdx.z;
    const float* A  = g_Bs + (size_t)i * CH * L;   // [K][M]
    const float* Bm = g_Fs + (size_t)i * CH * L;   // [K][N]
    float* Cc = g_A + (size_t)i * LLn;
    int m0 = blockIdx.y * 128, n0 = blockIdx.x * 128;
    __shared__ float sA[16][128], sB[16][128];
    int tid = threadIdx.x;
    int tx = tid & 15, ty = tid >> 4;
    int lr = tid >> 5, lc = (tid & 31) << 2;
    // 8x8 accumulators as 8x4 packed f32x2
    __align__(16) unsigned long long acc2[8][4];
#pragma unroll
    for (int mi = 0; mi < 8; ++mi)
#pragma unroll
        for (int ni = 0; ni < 4; ++ni) acc2[mi][ni] = 0ULL;

    for (int k0 = 0; k0 < CH; k0 += 16) {
#pragma unroll
        for (int sdx = 0; sdx < 2; ++sdx) {
            int kk = lr + sdx * 8;
            *(float4*)&sA[kk][lc] = *(const float4*)&A [(size_t)(k0 + kk) * L + m0 + lc];
            *(float4*)&sB[kk][lc] = *(const float4*)&Bm[(size_t)(k0 + kk) * L + n0 + lc];
        }
        __syncthreads();
#pragma unroll
        for (int kk = 0; kk < 16; ++kk) {
            __align__(16) float av[8], bv[8];
            *(float4*)&av[0] = *(float4*)&sA[kk][ty * 8];
            *(float4*)&av[4] = *(float4*)&sA[kk][ty * 8 + 4];
            *(float4*)&bv[0] = *(float4*)&sB[kk][tx * 8];
            *(float4*)&bv[4] = *(float4*)&sB[kk][tx * 8 + 4];
            const unsigned long long* bp = (const unsigned long long*)bv;
#pragma unroll
            for (int mi = 0; mi < 8; ++mi) {
                unsigned long long a2;
                asm("mov.b64 %0, {%1, %1};" : "=l"(a2) : "f"(av[mi]));
#pragma unroll
                for (int ni = 0; ni < 4; ++ni)
                    asm("fma.rn.f32x2 %0, %1, %2, %0;" : "+l"(acc2[mi][ni]) : "l"(a2), "l"(bp[ni]));
            }
        }
        __syncthreads();
    }
#pragma unroll
    for (int mi = 0; mi < 8; ++mi) {
        float* cp = &Cc[(size_t)(m0 + ty * 8 + mi) * L + n0 + tx * 8];
        const float* ap = (const float*)acc2[mi];
        *(float4*)cp       = *(const float4*)&ap[0];
        *(float4*)(cp + 4) = *(const float4*)&ap[4];
    }
}

// ================= stencil 1: 9-tap masked diagonal band of G, * invn[a] =================
// block: 256 b-cols x 64 a-rows (looped) for L2 tap reuse
__global__ __launch_bounds__(256) void k_corr(void) {
    int b = blockIdx.x * 256 + threadIdx.x;
    int ch = blockIdx.y, i = blockIdx.z;
    const float* src = g_A + (size_t)i * LLn;
    float* dst = g_B2 + (size_t)i * LLn;
    int r2 = b / S, c2 = b % S;
    for (int rr = 0; rr < 64; ++rr) {
        int a = ch * 64 + rr;
        int r1 = a / S, c1 = a % S;
        float s = 0.f;
#pragma unroll
        for (int dr = -1; dr <= 1; ++dr) {
            if ((unsigned)(r1 + dr) >= S || (unsigned)(r2 + dr) >= S) continue;
#pragma unroll
            for (int dc = -1; dc <= 1; ++dc) {
                if ((unsigned)(c1 + dc) >= S || (unsigned)(c2 + dc) >= S) continue;
                int off = dr * S + dc;
                s += src[(size_t)(a + off) * L + (b + off)];
            }
        }
        dst[(size_t)a * L + b] = s * g_invn[i * L + a];
    }
}

// ================= stencil 2: fused fuse_diag x2 + logit scale + column chunk-max =======
__global__ __launch_bounds__(256) void k_fuse(void) {
    int b = blockIdx.x * 256 + threadIdx.x;
    int ch = blockIdx.y, i = blockIdx.z;
    const float* src = g_B2 + (size_t)i * LLn;
    float* dst = g_A + (size_t)i * LLn;
    int bT = (b % S) * S + b / S;
    float pm = -1e30f;
    for (int rr = 0; rr < 64; ++rr) {
        int a = ch * 64 + rr;
        int aT = (a % S) * S + a / S;
        float s = 0.f;
#pragma unroll
        for (int d2 = -1; d2 <= 1; ++d2) {
            int ta = aT + d2, tb = bT + d2;
            if ((unsigned)ta >= L || (unsigned)tb >= L) continue;
            int A2 = (ta % S) * S + ta / S;
            int B2 = (tb % S) * S + tb / S;
#pragma unroll
            for (int d1 = -1; d1 <= 1; ++d1) {
                int x = A2 + d1, y = B2 + d1;
                if ((unsigned)x >= L || (unsigned)y >= L) continue;
                s += src[(size_t)x * L + y];
            }
        }
        float lg = s * 10.0f * g_mmv[i * L + a];
        dst[(size_t)a * L + b] = lg;
        pm = fmaxf(pm, lg);
    }
    g_pmax[(i * CHK + ch) * L + b] = pm;
}

// ================= softmax: partial sums + sparse candidate extraction =================
__global__ void k_ext(void) {
    int b = blockIdx.x * 256 + threadIdx.x;
    int ch = blockIdx.y, i = blockIdx.z;
    const float* src = g_A + (size_t)i * LLn;
    float m = -1e30f;
#pragma unroll
    for (int c2 = 0; c2 < CHK; ++c2)
        m = fmaxf(m, g_pmax[(i * CHK + c2) * L + b]);
    float s = 0.f;
    int n = 0;
    size_t base = ((size_t)(i * L + b) * CHK + ch) * CR;
    for (int r = 0; r < CR; ++r) {
        int a = ch * CR + r;
        float d = src[(size_t)a * L + b] - m;
        if (d > -25.0f) {
            float e = __expf(d);
            s += e;
            if (g_mmv[i * L + a] > 0.5f) {
                g_lidx[base + n] = a;
                g_lw [base + n] = e;
                n++;
            }
        }
    }
    g_psum[(i * CHK + ch) * L + b] = s;
    g_ccnt[(i * CHK + ch) * L + b] = n;
}

// merge chunk lists -> dense list with normalized weights baked in
__global__ void k_comp(void) {
    int idx = blockIdx.x * 256 + threadIdx.x;   // NB*L
    int i = idx / L, b = idx % L;
    float s = 0.f;
#pragma unroll
    for (int ch = 0; ch < CHK; ++ch)
        s += g_psum[(i * CHK + ch) * L + b];
    float inv = 1.0f / s;
    int n = 0;
    size_t sbase = (size_t)(i * L + b) * CHK * CR;
    size_t dbase = (size_t)(i * L + b) * DCAP;
    for (int ch = 0; ch < CHK; ++ch) {
        int c = g_ccnt[(i * CHK + ch) * L + b];
        for (int j = 0; j < c; ++j) {
            if (n < DCAP) {
                g_didx[dbase + n] = g_lidx[sbase + ch * CR + j];
                g_dw [dbase + n] = g_lw [sbase + ch * CR + j] * inv;
            }
            n++;
        }
    }
    g_dn[idx] = n < DCAP ? n : DCAP;
}

// ================= sparse transposed-conv gather =================
__global__ __launch_bounds__(128) void k_out(float* __restrict__ out) {
    int p = blockIdx.x;            // 0..HH*WW-1
    int i = blockIdx.y;
    int c = threadIdx.x;
    int oy = p / WW, ox = p % WW;
    int ua = oy / 2 - 1 + (oy & 1);
    int va = ox / 2 - 1 + (ox & 1);
    float acc = 0.f;
    const float* bcl = g_bcl + (size_t)i * HH * WW * CH;
#pragma unroll
    for (int du = 0; du < 2; ++du) {
        int uu = ua + du;
        if ((unsigned)uu >= S) continue;
#pragma unroll
        for (int dv = 0; dv < 2; ++dv) {
            int vv = va + dv;
            if ((unsigned)vv >= S) continue;
            int bcol = uu * S + vv;
            int n = g_dn[i * L + bcol];
            size_t db = (size_t)(i * L + bcol) * DCAP;
            for (int j = 0; j < n; ++j) {
                int a   = g_didx[db + j];
                float w = g_dw [db + j];
                int r1 = a / S, c1 = a % S;
                int Y = oy + 2 * (r1 - uu);
                int X = ox + 2 * (c1 - vv);
                if ((unsigned)Y < HH && (unsigned)X < WW)
                    acc += w * bcl[((size_t)Y * WW + X) * CH + c];
            }
        }
    }
    out[((size_t)(i * CH + c) * HH + oy) * WW + ox] = acc * 0.25f;
}

extern "C" void kernel_launch(void* const* d_in, const int* in_sizes, int n_in,
                              void* d_out, int out_size) {
    (void)in_sizes; (void)n_in; (void)out_size;
    const float* b    = (const float*)d_in[0];
    const float* f    = (const float*)d_in[1];
    const float* mask = (const float*)d_in[2];
    float* out = (float*)d_out;

    k_sub<<<NB * CH * L / 256, 256>>>(b, f);
    k_bcl<<<NB * CH * HH * WW / 256, 256>>>(b);
    k_sq  <<<NB * L / 256, 256>>>();
    k_norm<<<NB * L / 256, 256>>>();
    k_mm  <<<NB * L / 256, 256>>>(mask);

    {
        dim3 gg(L / 128, L / 128, NB);
        k_gemm<<<gg, 256>>>();
    }

    {
        dim3 gs(L / 256, CHK, NB);   // 64 a-rows per block, looped
        k_corr<<<gs, 256>>>();
        k_fuse<<<gs, 256>>>();
    }

    {
        dim3 gc(L / 256, CHK, NB);
        k_ext<<<gc, 256>>>();
        k_comp<<<NB * L / 256, 256>>>();
    }

    dim3 go(HH * WW, NB);
    k_out<<<go, 128>>>(out);
}

// round 11
// speedup vs baseline: 1.2693x; 1.0070x over previous
#include <cuda_runtime.h>
#include <math.h>
#include <stdint.h>

#define NB 4
#define CH 128
#define HH 96
#define WW 96
#define S  48
#define L  2304
#define LLn 5308416   // L*L
#define CHK 36
#define CR  64
#define DCAP 128

// ---- scratch (static device globals; no allocation) ----
__device__ float g_A [(size_t)NB * LLn];
__device__ float g_B2[(size_t)NB * LLn];
__device__ float g_Bs[NB * CH * L];
__device__ float g_Fs[NB * CH * L];
__device__ float g_bcl[NB * HH * WW * CH];
__device__ float g_sq [NB * L];
__device__ float g_invn[NB * L];
__device__ float g_mmv[NB * L];
__device__ float g_pmax[NB * CHK * L];
__device__ float g_psum[NB * CHK * L];
__device__ int   g_ccnt[NB * CHK * L];
__device__ int   g_lidx[(size_t)NB * L * CHK * CR];
__device__ float g_lw  [(size_t)NB * L * CHK * CR];
__device__ int   g_dn  [NB * L];
__device__ int   g_didx[(size_t)NB * L * DCAP];
__device__ float g_dw  [(size_t)NB * L * DCAP];

// ================= prep kernels =================
__global__ void k_sub(const float* __restrict__ b, const float* __restrict__ f) {
    int idx = blockIdx.x * blockDim.x + threadIdx.x;   // NB*CH*L
    int l = idx % L;
    int t = idx / L;
    int c = t % CH;
    int i = t / CH;
    int r = l / S, cc = l % S;
    int src = ((i * CH + c) * HH + 2 * r) * WW + 2 * cc;
    g_Bs[idx] = b[src];
    g_Fs[idx] = f[src];
}

__global__ void k_bcl(const float* __restrict__ b) {
    int idx = blockIdx.x * blockDim.x + threadIdx.x;   // NB*CH*HH*WW
    int x = idx % WW;
    int t = idx / WW;
    int y = t % HH;
    int u = t / HH;
    int c = u % CH;
    int i = u / CH;
    g_bcl[((i * HH + y) * WW + x) * CH + c] = b[idx];
}

__global__ void k_sq(void) {
    int idx = blockIdx.x * blockDim.x + threadIdx.x;   // NB*L
    int i = idx / L, l = idx % L;
    const float* p = g_Bs + (size_t)i * CH * L + l;
    float s = 0.f;
#pragma unroll 8
    for (int c = 0; c < CH; ++c) { float v = p[(size_t)c * L]; s += v * v; }
    g_sq[idx] = s;
}

__global__ void k_norm(void) {
    int idx = blockIdx.x * blockDim.x + threadIdx.x;
    int i = idx / L, l = idx % L;
    int r = l / S, c = l % S;
    float s = 0.f;
    for (int dr = -1; dr <= 1; ++dr)
        for (int dc = -1; dc <= 1; ++dc) {
            int rr = r + dr, cc = c + dc;
            if ((unsigned)rr < S && (unsigned)cc < S) s += g_sq[i * L + rr * S + cc];
        }
    g_invn[idx] = rsqrtf(s + 0.1152f);
}

__global__ void k_mm(const float* __restrict__ mask) {
    int idx = blockIdx.x * blockDim.x + threadIdx.x;
    int i = idx / L, l = idx % L;
    int r = l / S, c = l % S;
    float s = 0.f;
    for (int dr = -1; dr <= 1; ++dr)
        for (int dc = -1; dc <= 1; ++dc) {
            int rr = r + dr, cc = c + dc;
            if ((unsigned)rr < S && (unsigned)cc < S)
                s += mask[i * HH * WW + (2 * rr) * WW + (2 * cc)];
        }
    g_mmv[idx] = (s * (1.0f / 9.0f) == 1.0f) ? 1.f : 0.f;
}

// ================= f32x2 GEMM: G = Bs^T * Fs, [L x L] per sample =================
__global__ __launch_bounds__(256, 2) void k_gemm(void) {
    int i = blockIdx.z;
    const float* A  = g_Bs + (size_t)i * CH * L;   // [K][M]
    const float* Bm = g_Fs + (size_t)i * CH * L;   // [K][N]
    float* Cc = g_A + (size_t)i * LLn;
    int m0 = blockIdx.y * 128, n0 = blockIdx.x * 128;
    __shared__ float sA[16][128], sB[16][128];
    int tid = threadIdx.x;
    int tx = tid & 15, ty = tid >> 4;
    int lr = tid >> 5, lc = (tid & 31) << 2;
    __align__(16) unsigned long long acc2[8][4];
#pragma unroll
    for (int mi = 0; mi < 8; ++mi)
#pragma unroll
        for (int ni = 0; ni < 4; ++ni) acc2[mi][ni] = 0ULL;

    for (int k0 = 0; k0 < CH; k0 += 16) {
#pragma unroll
        for (int sdx = 0; sdx < 2; ++sdx) {
            int kk = lr + sdx * 8;
            *(float4*)&sA[kk][lc] = *(const float4*)&A [(size_t)(k0 + kk) * L + m0 + lc];
            *(float4*)&sB[kk][lc] = *(const float4*)&Bm[(size_t)(k0 + kk) * L + n0 + lc];
        }
        __syncthreads();
#pragma unroll
        for (int kk = 0; kk < 16; ++kk) {
            __align__(16) float av[8], bv[8];
            *(float4*)&av[0] = *(float4*)&sA[kk][ty * 8];
            *(float4*)&av[4] = *(float4*)&sA[kk][ty * 8 + 4];
            *(float4*)&bv[0] = *(float4*)&sB[kk][tx * 8];
            *(float4*)&bv[4] = *(float4*)&sB[kk][tx * 8 + 4];
            const unsigned long long* bp = (const unsigned long long*)bv;
#pragma unroll
            for (int mi = 0; mi < 8; ++mi) {
                unsigned long long a2;
                asm("mov.b64 %0, {%1, %1};" : "=l"(a2) : "f"(av[mi]));
#pragma unroll
                for (int ni = 0; ni < 4; ++ni)
                    asm("fma.rn.f32x2 %0, %1, %2, %0;" : "+l"(acc2[mi][ni]) : "l"(a2), "l"(bp[ni]));
            }
        }
        __syncthreads();
    }
#pragma unroll
    for (int mi = 0; mi < 8; ++mi) {
        float* cp = &Cc[(size_t)(m0 + ty * 8 + mi) * L + n0 + tx * 8];
        const float* ap = (const float*)acc2[mi];
        *(float4*)cp       = *(const float4*)&ap[0];
        *(float4*)(cp + 4) = *(const float4*)&ap[4];
    }
}

// ================= stencil 1: 9-tap masked diagonal band of G, * invn[a] =================
__global__ __launch_bounds__(256) void k_corr(void) {
    int b = blockIdx.x * 256 + threadIdx.x;
    int ch = blockIdx.y, i = blockIdx.z;
    const float* src = g_A + (size_t)i * LLn;
    float* dst = g_B2 + (size_t)i * LLn;
    int r2 = b / S, c2 = b % S;
    for (int rr = 0; rr < 64; ++rr) {
        int a = ch * 64 + rr;
        int r1 = a / S, c1 = a % S;
        float s = 0.f;
#pragma unroll
        for (int dr = -1; dr <= 1; ++dr) {
            if ((unsigned)(r1 + dr) >= S || (unsigned)(r2 + dr) >= S) continue;
#pragma unroll
            for (int dc = -1; dc <= 1; ++dc) {
                if ((unsigned)(c1 + dc) >= S || (unsigned)(c2 + dc) >= S) continue;
                int off = dr * S + dc;
                s += src[(size_t)(a + off) * L + (b + off)];
            }
        }
        dst[(size_t)a * L + b] = s * g_invn[i * L + a];
    }
}

// ===== stencil 2: fused fuse_diag x2 + logit scale + per-chunk column max =====
__global__ __launch_bounds__(256) void k_fuse(void) {
    int b = blockIdx.x * 256 + threadIdx.x;
    int ch = blockIdx.y, i = blockIdx.z;
    const float* src = g_B2 + (size_t)i * LLn;
    float* dst = g_A + (size_t)i * LLn;
    int bT = (b % S) * S + b / S;
    float pm = -1e30f;
    for (int rr = 0; rr < CR; ++rr) {
        int a = ch * CR + rr;
        int aT = (a % S) * S + a / S;
        float s = 0.f;
#pragma unroll
        for (int d2 = -1; d2 <= 1; ++d2) {
            int ta = aT + d2, tb = bT + d2;
            if ((unsigned)ta >= L || (unsigned)tb >= L) continue;
            int A2 = (ta % S) * S + ta / S;
            int B2 = (tb % S) * S + tb / S;
#pragma unroll
            for (int d1 = -1; d1 <= 1; ++d1) {
                int x = A2 + d1, y = B2 + d1;
                if ((unsigned)x >= L || (unsigned)y >= L) continue;
                s += src[(size_t)x * L + y];
            }
        }
        float lg = s * 10.0f * g_mmv[i * L + a];
        dst[(size_t)a * L + b] = lg;
        pm = fmaxf(pm, lg);
    }
    g_pmax[(i * CHK + ch) * L + b] = pm;
}

// ===== softmax: global max from pmax, chunk-skip, partial sums + candidates =====
__global__ void k_ext(void) {
    int b = blockIdx.x * 256 + threadIdx.x;
    int ch = blockIdx.y, i = blockIdx.z;
    float pmc = g_pmax[(i * CHK + ch) * L + b];
    float m = -1e30f;
#pragma unroll
    for (int c2 = 0; c2 < CHK; ++c2)
        m = fmaxf(m, g_pmax[(i * CHK + c2) * L + b]);
    // chunk entirely below threshold: contributes <= 64*e^-25 to sum, no candidates
    if (pmc < m - 25.0f) {
        g_psum[(i * CHK + ch) * L + b] = 0.f;
        g_ccnt[(i * CHK + ch) * L + b] = 0;
        return;
    }
    const float* src = g_A + (size_t)i * LLn;
    float s = 0.f;
    int n = 0;
    size_t base = ((size_t)(i * L + b) * CHK + ch) * CR;
    for (int r = 0; r < CR; ++r) {
        int a = ch * CR + r;
        float d = src[(size_t)a * L + b] - m;
        if (d > -25.0f) {
            float e = __expf(d);
            s += e;
            if (g_mmv[i * L + a] > 0.5f) {
                g_lidx[base + n] = a;
                g_lw [base + n] = e;
                n++;
            }
        }
    }
    g_psum[(i * CHK + ch) * L + b] = s;
    g_ccnt[(i * CHK + ch) * L + b] = n;
}

// merge chunk lists -> dense list with normalized weights baked in
__global__ void k_comp(void) {
    int idx = blockIdx.x * 256 + threadIdx.x;   // NB*L
    int i = idx / L, b = idx % L;
    float s = 0.f;
#pragma unroll
    for (int ch = 0; ch < CHK; ++ch)
        s += g_psum[(i * CHK + ch) * L + b];
    float inv = 1.0f / s;
    int n = 0;
    size_t sbase = (size_t)(i * L + b) * CHK * CR;
    size_t dbase = (size_t)(i * L + b) * DCAP;
    for (int ch = 0; ch < CHK; ++ch) {
        int c = g_ccnt[(i * CHK + ch) * L + b];
        for (int j = 0; j < c; ++j) {
            if (n < DCAP) {
                g_didx[dbase + n] = g_lidx[sbase + ch * CR + j];
                g_dw [dbase + n] = g_lw [sbase + ch * CR + j] * inv;
            }
            n++;
        }
    }
    g_dn[idx] = n < DCAP ? n : DCAP;
}

// ================= sparse transposed-conv gather =================
__global__ __launch_bounds__(128) void k_out(float* __restrict__ out) {
    int p = blockIdx.x;            // 0..HH*WW-1
    int i = blockIdx.y;
    int c = threadIdx.x;
    int oy = p / WW, ox = p % WW;
    int ua = oy / 2 - 1 + (oy & 1);
    int va = ox / 2 - 1 + (ox & 1);
    float acc = 0.f;
    const float* bcl = g_bcl + (size_t)i * HH * WW * CH;
#pragma unroll
    for (int du = 0; du < 2; ++du) {
        int uu = ua + du;
        if ((unsigned)uu >= S) continue;
#pragma unroll
        for (int dv = 0; dv < 2; ++dv) {
            int vv = va + dv;
            if ((unsigned)vv >= S) continue;
            int bcol = uu * S + vv;
            int n = g_dn[i * L + bcol];
            size_t db = (size_t)(i * L + bcol) * DCAP;
            for (int j = 0; j < n; ++j) {
                int a   = g_didx[db + j];
                float w = g_dw [db + j];
                int r1 = a / S, c1 = a % S;
                int Y = oy + 2 * (r1 - uu);
                int X = ox + 2 * (c1 - vv);
                if ((unsigned)Y < HH && (unsigned)X < WW)
                    acc += w * bcl[((size_t)Y * WW + X) * CH + c];
            }
        }
    }
    out[((size_t)(i * CH + c) * HH + oy) * WW + ox] = acc * 0.25f;
}

extern "C" void kernel_launch(void* const* d_in, const int* in_sizes, int n_in,
                              void* d_out, int out_size) {
    (void)in_sizes; (void)n_in; (void)out_size;
    const float* b    = (const float*)d_in[0];
    const float* f    = (const float*)d_in[1];
    const float* mask = (const float*)d_in[2];
    float* out = (float*)d_out;

    k_sub<<<NB * CH * L / 256, 256>>>(b, f);
    k_bcl<<<NB * CH * HH * WW / 256, 256>>>(b);
    k_sq  <<<NB * L / 256, 256>>>();
    k_norm<<<NB * L / 256, 256>>>();
    k_mm  <<<NB * L / 256, 256>>>(mask);

    {
        dim3 gg(L / 128, L / 128, NB);
        k_gemm<<<gg, 256>>>();
    }

    {
        dim3 gs(L / 256, CHK, NB);   // 64 a-rows per block, looped
        k_corr<<<gs, 256>>>();
        k_fuse<<<gs, 256>>>();
    }

    {
        dim3 gc(L / 256, CHK, NB);
        k_ext<<<gc, 256>>>();
        k_comp<<<NB * L / 256, 256>>>();
    }

    dim3 go(HH * WW, NB);
    k_out<<<go, 128>>>(out);
}